// round 12
// baseline (speedup 1.0000x reference)
#include <cuda_runtime.h>
#include <math.h>
#include <cstdint>

// Problem constants
#define NBLK 512
#define BQ   32
#define HH   16
#define DD   576
#define DD4  144
#define DVV  512
#define BSS  128
#define QSCALE 0.07216878364870322f  // 192^-0.5

typedef unsigned long long ull;

// Scratch (device globals — no allocation allowed)
__device__ float g_oacc[NBLK * HH * DVV];
__device__ float g_bm[NBLK * HH];
__device__ float g_bs[NBLK * HH];

// ---------------- helpers ----------------
__device__ __forceinline__ uint32_t smem_u32(const void* p) {
    uint32_t a;
    asm("{ .reg .u64 t; cvta.to.shared.u64 t, %1; cvt.u32.u64 %0, t; }" : "=r"(a) : "l"(p));
    return a;
}
__device__ __forceinline__ void cp16(uint32_t dst, const void* src) {
    asm volatile("cp.async.cg.shared.global [%0], [%1], 16;" :: "r"(dst), "l"(src));
}
#define CP_COMMIT() asm volatile("cp.async.commit_group;" ::: "memory")
#define CP_WAIT(n)  asm volatile("cp.async.wait_group %0;" :: "n"(n) : "memory")

__device__ __forceinline__ void fma2(ull& d, ull a, ull b) {
    asm("fma.rn.f32x2 %0, %1, %2, %0;" : "+l"(d) : "l"(a), "l"(b));
}
__device__ __forceinline__ float lo_f(ull v) { return __uint_as_float((unsigned)v); }
__device__ __forceinline__ float hi_f(ull v) { return __uint_as_float((unsigned)(v >> 32)); }
__device__ __forceinline__ ull dup2(float v) {
    unsigned u = __float_as_uint(v);
    return ((ull)u << 32) | u;
}

// ---------------- SMEM layout (bytes) ----------------
// [0, 36864)      : K chunk double buffer: buf b at b*18432, 128 rows x 9 float4
//                   (Pass C: V double buffer, buf b at b*16384, 8 rows x 128 f4)
// [36864, 41472)  : Q chunk double buffer: buf b at QOFF + b*2304, 16 x 9 float4
// [41472, 49920)  : attn f32 [16][132]
#define KBUFB 18432
#define KSTR  9
#define QOFF  36864
#define QBUFB 2304
#define ATTOFF 41472
#define ATT_STRIDE 132
#define SMEM_BYTES 49920

#define CHUNK_F4 8    // 32 d-floats per chunk
#define NCH 18        // 576 / 32

__global__ __launch_bounds__(256, 3) void mla_block_kernel(
    const float* __restrict__ query,
    const float* __restrict__ key_cache,
    const float* __restrict__ block_bias,
    const int* __restrict__ block_list,
    const int* __restrict__ block_groups)
{
    extern __shared__ char smem[];
    const uint32_t sbase = smem_u32(smem);
    const int t = threadIdx.x;
    const int n = blockIdx.x;
    const int b = block_groups[n];
    const float4* kvb4 = (const float4*)(key_cache + (long)block_list[n] * (BSS * DD));
    const float4* q4 = (const float4*)query;
    float* attn = (float*)(smem + ATTOFF);

    // q loader mapping (first 128 threads)
    const int ls = t >> 3, lk = t & 7;

    // ---- Pass A issue: chunk c -> buffer c&1 (K 1024 f4 + Q 128 f4)
    auto issueA = [&](int c) {
        uint32_t kb = sbase + (unsigned)(c & 1) * KBUFB;
        #pragma unroll
        for (int j = 0; j < 4; j++) {
            int i = t + j * 256;
            int s = i >> 3, k = i & 7;
            cp16(kb + (unsigned)(s * KSTR + k) * 16,
                 kvb4 + (long)s * DD4 + c * CHUNK_F4 + k);
        }
        if (t < 128)
            cp16(sbase + QOFF + (unsigned)(c & 1) * QBUFB + (unsigned)(ls * KSTR + lk) * 16,
                 q4 + (long)(b * HH + ls) * DD4 + c * CHUNK_F4 + lk);
        CP_COMMIT();
    };
    // ---- Pass C issue: V tile tl -> buffer tl&1 (8 rows x 128 f4)
    auto issueC = [&](int tl) {
        uint32_t vbuf = sbase + (unsigned)(tl & 1) * 16384;
        #pragma unroll
        for (int j = 0; j < 4; j++) {
            int i = t + j * 256;
            int r = i >> 7, col = i & 127;
            cp16(vbuf + (unsigned)i * 16,
                 kvb4 + (long)(tl * 8 + r) * DD4 + col);
        }
        CP_COMMIT();
    };

    // ================= Pass A: attn = scale * q . kv =======================
    // thread tile: h = hq + 4*i (i<4), s = sq + 64*j (j<2)
    // warp: sq consecutive (8 values) -> bank step 36 mod 32 = 4, conflict-free
    const int hq = t & 3;
    const int sq = t >> 2;   // 0..63

    ull acc2[4][2];
    #pragma unroll
    for (int i = 0; i < 4; i++) { acc2[i][0] = 0ull; acc2[i][1] = 0ull; }

    issueA(0);
    issueA(1);

    for (int c = 0; c < NCH; c++) {
        if (c < NCH - 1) CP_WAIT(1); else CP_WAIT(0);
        __syncthreads();

        // Early V prefetch during last K chunk's compute (buffer 0 free).
        if (c == NCH - 1) issueC(0);

        const float4* kvs4 = (const float4*)(smem + (c & 1) * KBUFB);
        const float4* qc4  = (const float4*)(smem + QOFF + (c & 1) * QBUFB);

        #pragma unroll
        for (int k4 = 0; k4 < 8; k4++) {
            ull qp[4][2], kp[2][2];
            #pragma unroll
            for (int i = 0; i < 4; i++) {
                ulonglong2 qq = *(const ulonglong2*)&qc4[(hq + 4 * i) * KSTR + k4];
                qp[i][0] = qq.x; qp[i][1] = qq.y;
            }
            #pragma unroll
            for (int j = 0; j < 2; j++) {
                ulonglong2 kk = *(const ulonglong2*)&kvs4[(sq + 64 * j) * KSTR + k4];
                kp[j][0] = kk.x; kp[j][1] = kk.y;
            }
            #pragma unroll
            for (int i = 0; i < 4; i++)
                #pragma unroll
                for (int j = 0; j < 2; j++) {
                    fma2(acc2[i][j], qp[i][0], kp[j][0]);
                    fma2(acc2[i][j], qp[i][1], kp[j][1]);
                }
        }
        __syncthreads();
        if (c + 2 < NCH) issueA(c + 2);
    }

    // merge lo+hi, apply scale, add bias, write attn
    #pragma unroll
    for (int j = 0; j < 2; j++) {
        int s = sq + 64 * j;
        float bias = block_bias[n * BSS + s];
        #pragma unroll
        for (int i = 0; i < 4; i++) {
            int h = hq + 4 * i;
            attn[h * ATT_STRIDE + s] =
                (lo_f(acc2[i][j]) + hi_f(acc2[i][j])) * QSCALE + bias;
        }
    }
    __syncthreads();

    // V tile 1 (buffer 1 free: K buf1 fully consumed pre-barrier)
    issueC(1);

    // ================= Pass B: per-(n,h) softmax (16 lanes per head) =======
    {
        int h = t >> 4, ln = t & 15;
        float m = -1e30f;
        #pragma unroll
        for (int r = 0; r < 8; r++)
            m = fmaxf(m, attn[h * ATT_STRIDE + ln + r * 16]);
        #pragma unroll
        for (int o = 8; o >= 1; o >>= 1)
            m = fmaxf(m, __shfl_xor_sync(0xffffffffu, m, o, 16));
        float l = 0.f;
        #pragma unroll
        for (int r = 0; r < 8; r++) {
            int idx = h * ATT_STRIDE + ln + r * 16;
            float p = __expf(attn[idx] - m);
            attn[idx] = p;
            l += p;
        }
        #pragma unroll
        for (int o = 8; o >= 1; o >>= 1)
            l += __shfl_xor_sync(0xffffffffu, l, o, 16);
        if (ln == 0) {
            g_bm[n * HH + h] = m;
            g_bs[n * HH + h] = l;
        }
    }

    // ================= Pass C: o = p @ v (f32x2, 16 tiles of 8 rows) =======
    // thread tile: h = hb + 4*i (i<4), v f4 cols {vb, vb+64}
    const int hb = t & 3;
    const int vb = t >> 2;   // 0..63

    ull o2[4][4];
    #pragma unroll
    for (int i = 0; i < 4; i++)
        #pragma unroll
        for (int p = 0; p < 4; p++) o2[i][p] = 0ull;

    for (int tl = 0; tl < 16; tl++) {
        if (tl < 15) CP_WAIT(1); else CP_WAIT(0);
        __syncthreads();

        const float4* vs4 = (const float4*)(smem + (tl & 1) * 16384);
        #pragma unroll
        for (int s = 0; s < 8; s++) {
            ull pd[4];
            #pragma unroll
            for (int i = 0; i < 4; i++)
                pd[i] = dup2(attn[(hb + 4 * i) * ATT_STRIDE + tl * 8 + s]);
            #pragma unroll
            for (int cc = 0; cc < 2; cc++) {
                ulonglong2 vv = *(const ulonglong2*)&vs4[s * 128 + vb + cc * 64];
                #pragma unroll
                for (int i = 0; i < 4; i++) {
                    fma2(o2[i][2 * cc],     pd[i], vv.x);
                    fma2(o2[i][2 * cc + 1], pd[i], vv.y);
                }
            }
        }
        __syncthreads();
        if (tl + 2 < 16) issueC(tl + 2);
    }

    // store partials (each thread: 2 float4s per h at columns vb, vb+64)
    #pragma unroll
    for (int i = 0; i < 4; i++) {
        int h = hb + 4 * i;
        ulonglong2* dst = (ulonglong2*)(g_oacc + ((long)(n * HH + h)) * DVV);
        ulonglong2 v0; v0.x = o2[i][0]; v0.y = o2[i][1];
        ulonglong2 v1; v1.x = o2[i][2]; v1.y = o2[i][3];
        dst[vb]      = v0;
        dst[vb + 64] = v1;
    }
}

// ---------------- combine: group b owns blocks b*16..b*16+15 ----------------
// 512 threads, thread owns one v-float; all 16 block loads in flight.
__global__ __launch_bounds__(512) void mla_combine_kernel(float* __restrict__ out)
{
    const int b = blockIdx.x, h = blockIdx.y, t = threadIdx.x;
    __shared__ float w[16];

    if (t < 16) {
        float m = g_bm[(b * 16 + t) * HH + h];
        float gmax = m;
        #pragma unroll
        for (int o = 8; o >= 1; o >>= 1)
            gmax = fmaxf(gmax, __shfl_xor_sync(0xffffu, gmax, o, 16));
        float e = __expf(m - gmax);
        float gsum = g_bs[(b * 16 + t) * HH + h] * e;
        #pragma unroll
        for (int o = 8; o >= 1; o >>= 1)
            gsum += __shfl_xor_sync(0xffffu, gsum, o, 16);
        w[t] = e / gsum;
    }
    __syncthreads();

    float v[16];
    #pragma unroll
    for (int j = 0; j < 16; j++)
        v[j] = g_oacc[((long)((b * 16 + j) * HH + h)) * DVV + t];

    float acc = 0.f;
    #pragma unroll
    for (int j = 0; j < 16; j++)
        acc += w[j] * v[j];
    out[((long)(b * HH + h)) * DVV + t] = acc;
}

// -----------------------------------------------------------------------------
extern "C" void kernel_launch(void* const* d_in, const int* in_sizes, int n_in,
                              void* d_out, int out_size)
{
    const float* query        = (const float*)d_in[0];
    const float* key_cache    = (const float*)d_in[1];
    const float* block_bias   = (const float*)d_in[3];
    const int*   block_list   = (const int*)d_in[4];
    const int*   block_groups = (const int*)d_in[5];
    float* out = (float*)d_out;

    cudaFuncSetAttribute(mla_block_kernel,
                         cudaFuncAttributeMaxDynamicSharedMemorySize, SMEM_BYTES);

    mla_block_kernel<<<NBLK, 256, SMEM_BYTES>>>(
        query, key_cache, block_bias, block_list, block_groups);
    mla_combine_kernel<<<dim3(BQ, HH), 512>>>(out);
}

// round 13
// speedup vs baseline: 1.2682x; 1.2682x over previous
#include <cuda_runtime.h>
#include <math.h>
#include <cstdint>

// Problem constants
#define NBLK 512
#define BQ   32
#define HH   16
#define DD   576
#define DD4  144
#define DVV  512
#define BSS  128
#define QSCALE 0.07216878364870322f  // 192^-0.5

typedef unsigned long long ull;

// Scratch (device globals — no allocation allowed)
__device__ float g_oacc[NBLK * HH * DVV];
__device__ float g_bm[NBLK * HH];
__device__ float g_bs[NBLK * HH];

// ---------------- helpers ----------------
__device__ __forceinline__ uint32_t smem_u32(const void* p) {
    uint32_t a;
    asm("{ .reg .u64 t; cvta.to.shared.u64 t, %1; cvt.u32.u64 %0, t; }" : "=r"(a) : "l"(p));
    return a;
}
__device__ __forceinline__ void cp16(uint32_t dst, const void* src) {
    asm volatile("cp.async.cg.shared.global [%0], [%1], 16;" :: "r"(dst), "l"(src));
}
#define CP_COMMIT() asm volatile("cp.async.commit_group;" ::: "memory")
#define CP_WAIT(n)  asm volatile("cp.async.wait_group %0;" :: "n"(n) : "memory")

__device__ __forceinline__ void fma2(ull& d, ull a, ull b) {
    asm("fma.rn.f32x2 %0, %1, %2, %0;" : "+l"(d) : "l"(a), "l"(b));
}
__device__ __forceinline__ float lo_f(ull v) { return __uint_as_float((unsigned)v); }
__device__ __forceinline__ float hi_f(ull v) { return __uint_as_float((unsigned)(v >> 32)); }
__device__ __forceinline__ ull dup2(float v) {
    unsigned u = __float_as_uint(v);
    return ((ull)u << 32) | u;
}

// ---------------- SMEM layout (bytes) ----------------
// [0, 36864)      : K chunk double buffer: buf b at b*18432, 128 rows x 9 float4
//                   (Pass C: V double buffer, buf b at b*16384, 8 rows x 128 f4)
// [36864, 41472)  : Q chunk double buffer: buf b at QOFF + b*2304, 16 x 9 float4
// [41472, 49920)  : attn f32 [16][132]
#define KBUFB 18432
#define KSTR  9
#define QOFF  36864
#define QBUFB 2304
#define ATTOFF 41472
#define ATT_STRIDE 132
#define SMEM_BYTES 49920

#define CHUNK_F4 8    // 32 d-floats per chunk
#define NCH 18        // 576 / 32

__global__ __launch_bounds__(128, 4) void mla_block_kernel(
    const float* __restrict__ query,
    const float* __restrict__ key_cache,
    const float* __restrict__ block_bias,
    const int* __restrict__ block_list,
    const int* __restrict__ block_groups)
{
    extern __shared__ char smem[];
    const uint32_t sbase = smem_u32(smem);
    const int t = threadIdx.x;
    const int n = blockIdx.x;
    const int b = block_groups[n];
    const float4* kvb4 = (const float4*)(key_cache + (long)block_list[n] * (BSS * DD));
    const float4* q4 = (const float4*)query;
    float* attn = (float*)(smem + ATTOFF);

    // q loader mapping
    const int ls = t >> 3, lk = t & 7;

    // ---- Pass A issue: chunk c -> buffer c&1 (K 1024 f4 + Q 16 f4)
    auto issueA = [&](int c) {
        uint32_t kb = sbase + (unsigned)(c & 1) * KBUFB;
        #pragma unroll
        for (int j = 0; j < 8; j++) {
            int i = t + j * 128;
            int s = i >> 3, k = i & 7;
            cp16(kb + (unsigned)(s * KSTR + k) * 16,
                 kvb4 + (long)s * DD4 + c * CHUNK_F4 + k);
        }
        cp16(sbase + QOFF + (unsigned)(c & 1) * QBUFB + (unsigned)(ls * KSTR + lk) * 16,
             q4 + (long)(b * HH + ls) * DD4 + c * CHUNK_F4 + lk);
        CP_COMMIT();
    };
    // ---- Pass C issue: V tile tl -> buffer tl&1 (8 rows x 128 f4)
    auto issueC = [&](int tl) {
        uint32_t vbuf = sbase + (unsigned)(tl & 1) * 16384;
        #pragma unroll
        for (int j = 0; j < 8; j++) {
            int i = t + j * 128;
            int r = i >> 7, col = i & 127;
            cp16(vbuf + (unsigned)i * 16,
                 kvb4 + (long)(tl * 8 + r) * DD4 + col);
        }
        CP_COMMIT();
    };

    // ================= Pass A: attn = scale * q . kv =======================
    // thread tile: h = hq + 4*i, s = sq + 32*j  (conflict-free LDS)
    const int hq = t & 3;
    const int sq = t >> 2;   // 0..31

    ull acc2[4][4];
    #pragma unroll
    for (int i = 0; i < 4; i++)
        #pragma unroll
        for (int j = 0; j < 4; j++) acc2[i][j] = 0ull;

    issueA(0);
    issueA(1);

    for (int c = 0; c < NCH; c++) {
        if (c < NCH - 1) CP_WAIT(1); else CP_WAIT(0);
        __syncthreads();

        // Early V prefetch during last K chunk's compute (buffer 0 free).
        if (c == NCH - 1) issueC(0);

        const float4* kvs4 = (const float4*)(smem + (c & 1) * KBUFB);
        const float4* qc4  = (const float4*)(smem + QOFF + (c & 1) * QBUFB);

        // software-pipelined over k4: operand sets A (even) / B (odd)
        ull qpA[4][2], kpA[4][2], qpB[4][2], kpB[4][2];

        #pragma unroll
        for (int i = 0; i < 4; i++) {
            ulonglong2 qq = *(const ulonglong2*)&qc4[(hq + 4 * i) * KSTR + 0];
            qpA[i][0] = qq.x; qpA[i][1] = qq.y;
            ulonglong2 kk = *(const ulonglong2*)&kvs4[(sq + 32 * i) * KSTR + 0];
            kpA[i][0] = kk.x; kpA[i][1] = kk.y;
        }

        #pragma unroll
        for (int k4 = 0; k4 < 8; k4 += 2) {
            // prefetch odd operand set (k4+1)
            #pragma unroll
            for (int i = 0; i < 4; i++) {
                ulonglong2 qq = *(const ulonglong2*)&qc4[(hq + 4 * i) * KSTR + k4 + 1];
                qpB[i][0] = qq.x; qpB[i][1] = qq.y;
                ulonglong2 kk = *(const ulonglong2*)&kvs4[(sq + 32 * i) * KSTR + k4 + 1];
                kpB[i][0] = kk.x; kpB[i][1] = kk.y;
            }
            // compute even (A)
            #pragma unroll
            for (int i = 0; i < 4; i++)
                #pragma unroll
                for (int j = 0; j < 4; j++) {
                    fma2(acc2[i][j], qpA[i][0], kpA[j][0]);
                    fma2(acc2[i][j], qpA[i][1], kpA[j][1]);
                }
            // prefetch next even operand set (k4+2)
            if (k4 + 2 < 8) {
                #pragma unroll
                for (int i = 0; i < 4; i++) {
                    ulonglong2 qq = *(const ulonglong2*)&qc4[(hq + 4 * i) * KSTR + k4 + 2];
                    qpA[i][0] = qq.x; qpA[i][1] = qq.y;
                    ulonglong2 kk = *(const ulonglong2*)&kvs4[(sq + 32 * i) * KSTR + k4 + 2];
                    kpA[i][0] = kk.x; kpA[i][1] = kk.y;
                }
            }
            // compute odd (B)
            #pragma unroll
            for (int i = 0; i < 4; i++)
                #pragma unroll
                for (int j = 0; j < 4; j++) {
                    fma2(acc2[i][j], qpB[i][0], kpB[j][0]);
                    fma2(acc2[i][j], qpB[i][1], kpB[j][1]);
                }
        }
        __syncthreads();
        if (c + 2 < NCH) issueA(c + 2);
    }

    // merge lo+hi, apply scale, add bias, write attn
    #pragma unroll
    for (int j = 0; j < 4; j++) {
        int s = sq + 32 * j;
        float bias = block_bias[n * BSS + s];
        #pragma unroll
        for (int i = 0; i < 4; i++) {
            int h = hq + 4 * i;
            attn[h * ATT_STRIDE + s] =
                (lo_f(acc2[i][j]) + hi_f(acc2[i][j])) * QSCALE + bias;
        }
    }
    __syncthreads();

    // V tile 1 (buffer 1 region free: K buf1 fully consumed pre-barrier)
    issueC(1);

    // ================= Pass B: per-(n,h) softmax ===========================
    {
        int h = t >> 3, ln = t & 7;
        float m = -1e30f;
        #pragma unroll
        for (int r = 0; r < 16; r++)
            m = fmaxf(m, attn[h * ATT_STRIDE + ln + r * 8]);
        #pragma unroll
        for (int o = 4; o >= 1; o >>= 1)
            m = fmaxf(m, __shfl_xor_sync(0xffffffffu, m, o, 8));
        float l = 0.f;
        #pragma unroll
        for (int r = 0; r < 16; r++) {
            int idx = h * ATT_STRIDE + ln + r * 8;
            float p = __expf(attn[idx] - m);
            attn[idx] = p;
            l += p;
        }
        #pragma unroll
        for (int o = 4; o >= 1; o >>= 1)
            l += __shfl_xor_sync(0xffffffffu, l, o, 8);
        if (ln == 0) {
            g_bm[n * HH + h] = m;
            g_bs[n * HH + h] = l;
        }
    }

    // ================= Pass C: o = p @ v (f32x2, 16 tiles of 8 rows) =======
    const int hb = t & 3;
    const int vb = t >> 2;   // 0..31

    ull o2[4][8];
    #pragma unroll
    for (int i = 0; i < 4; i++)
        #pragma unroll
        for (int p = 0; p < 8; p++) o2[i][p] = 0ull;

    for (int tl = 0; tl < 16; tl++) {
        if (tl < 15) CP_WAIT(1); else CP_WAIT(0);
        __syncthreads();

        const float4* vs4 = (const float4*)(smem + (tl & 1) * 16384);
        #pragma unroll
        for (int s = 0; s < 8; s++) {
            ull pd[4];
            #pragma unroll
            for (int i = 0; i < 4; i++)
                pd[i] = dup2(attn[(hb + 4 * i) * ATT_STRIDE + tl * 8 + s]);
            #pragma unroll
            for (int cc = 0; cc < 4; cc++) {
                ulonglong2 vv = *(const ulonglong2*)&vs4[s * 128 + vb + cc * 32];
                #pragma unroll
                for (int i = 0; i < 4; i++) {
                    fma2(o2[i][2 * cc],     pd[i], vv.x);
                    fma2(o2[i][2 * cc + 1], pd[i], vv.y);
                }
            }
        }
        __syncthreads();
        if (tl + 2 < 16) issueC(tl + 2);
    }

    // store partials (each thread: 4 float4s per h at column vb + cc*32)
    #pragma unroll
    for (int i = 0; i < 4; i++) {
        int h = hb + 4 * i;
        ulonglong2* dst = (ulonglong2*)(g_oacc + ((long)(n * HH + h)) * DVV);
        #pragma unroll
        for (int cc = 0; cc < 4; cc++) {
            ulonglong2 v; v.x = o2[i][2 * cc]; v.y = o2[i][2 * cc + 1];
            dst[vb + cc * 32] = v;
        }
    }
}

// ---------------- combine: group b owns blocks b*16..b*16+15 ----------------
// 512 threads, thread owns one v-float; all 16 block loads in flight.
__global__ __launch_bounds__(512) void mla_combine_kernel(float* __restrict__ out)
{
    const int b = blockIdx.x, h = blockIdx.y, t = threadIdx.x;
    __shared__ float w[16];

    if (t < 16) {
        float m = g_bm[(b * 16 + t) * HH + h];
        float gmax = m;
        #pragma unroll
        for (int o = 8; o >= 1; o >>= 1)
            gmax = fmaxf(gmax, __shfl_xor_sync(0xffffu, gmax, o, 16));
        float e = __expf(m - gmax);
        float gsum = g_bs[(b * 16 + t) * HH + h] * e;
        #pragma unroll
        for (int o = 8; o >= 1; o >>= 1)
            gsum += __shfl_xor_sync(0xffffu, gsum, o, 16);
        w[t] = e / gsum;
    }
    __syncthreads();

    float v[16];
    #pragma unroll
    for (int j = 0; j < 16; j++)
        v[j] = g_oacc[((long)((b * 16 + j) * HH + h)) * DVV + t];

    float acc = 0.f;
    #pragma unroll
    for (int j = 0; j < 16; j++)
        acc += w[j] * v[j];
    out[((long)(b * HH + h)) * DVV + t] = acc;
}

// -----------------------------------------------------------------------------
extern "C" void kernel_launch(void* const* d_in, const int* in_sizes, int n_in,
                              void* d_out, int out_size)
{
    const float* query        = (const float*)d_in[0];
    const float* key_cache    = (const float*)d_in[1];
    const float* block_bias   = (const float*)d_in[3];
    const int*   block_list   = (const int*)d_in[4];
    const int*   block_groups = (const int*)d_in[5];
    float* out = (float*)d_out;

    cudaFuncSetAttribute(mla_block_kernel,
                         cudaFuncAttributeMaxDynamicSharedMemorySize, SMEM_BYTES);

    mla_block_kernel<<<NBLK, 128, SMEM_BYTES>>>(
        query, key_cache, block_bias, block_list, block_groups);
    mla_combine_kernel<<<dim3(BQ, HH), 512>>>(out);
}